// round 8
// baseline (speedup 1.0000x reference)
#include <cuda_runtime.h>
#include <cstdint>

#define S_    512
#define P_    196
#define Q_    48
#define CB_   8
#define R_    32
#define C_    10
#define NMID  6

#define THREADS 1024

// shared memory layout (floats)
#define OFF_X   0                      // 9408   x[p][q]
#define OFF_M   9408                   // 12544  M[p][ab]
#define OFF_G   21952                  // 16384  G tile [ab(64)][col(256)] / partials
#define OFF_CK  38336                  // 3072   Ck as [q][a*8+b]
#define OFF_ST  41408                  // 2*2560 state[a*320 + l*10 + c]
#define OFF_OUT 46528                  // 16
#define SMEM_FLOATS 46544

// M row stride in ulonglong2 units: 64 floats = 16 ulonglong2
#define MSTRIDE 16

__device__ __forceinline__ void ffma2(uint64_t& d, uint64_t a, uint64_t b) {
    asm("fma.rn.f32x2 %0, %1, %2, %0;" : "+l"(d) : "l"(a), "l"(b));
}
__device__ __forceinline__ uint64_t bcast2(float v) {
    uint64_t r; unsigned u = __float_as_uint(v);
    asm("mov.b64 %0, {%1, %1};" : "=l"(r) : "r"(u));
    return r;
}
__device__ __forceinline__ float2 unpack2(uint64_t v) {
    float2 f;
    asm("mov.b64 {%0, %1}, %2;" : "=f"(f.x), "=f"(f.y) : "l"(v));
    return f;
}

// 8 packed-FMA2: acc[pr*4+j] (+)= (m pair pr) * bcast(av lane j); MA = 4 rows (2 pairs)
#define FFMA2_BLK8(ACC, MA, AV)                                        \
    {                                                                  \
        uint64_t b0 = bcast2(AV.x), b1 = bcast2(AV.y);                 \
        uint64_t b2 = bcast2(AV.z), b3 = bcast2(AV.w);                 \
        ffma2(ACC[0], MA.x, b0); ffma2(ACC[1], MA.x, b1);              \
        ffma2(ACC[2], MA.x, b2); ffma2(ACC[3], MA.x, b3);              \
        ffma2(ACC[4], MA.y, b0); ffma2(ACC[5], MA.y, b1);              \
        ffma2(ACC[6], MA.y, b2); ffma2(ACC[7], MA.y, b3);              \
    }

__global__ void __launch_bounds__(THREADS, 1)
tctl_kernel(const float* __restrict__ x,
            const float* __restrict__ cf,   // [Q][CB]
            const float* __restrict__ cm,   // [NMID][CB][Q][CB]
            const float* __restrict__ cl,   // [CB][Q]
            const float* __restrict__ tf,   // [C][P][R]
            const float* __restrict__ tm,   // [NMID][R][P][R]
            const float* __restrict__ tl,   // [R][P]
            float* __restrict__ out)        // [S][C]
{
    extern __shared__ float smem[];
    float* sx     = smem + OFF_X;
    float* sM     = smem + OFF_M;
    float* sG     = smem + OFF_G;
    float* sCk    = smem + OFF_CK;
    float* sState = smem + OFF_ST;
    float* sOut   = smem + OFF_OUT;

    const int tid = threadIdx.x;
    const int s   = blockIdx.x;

    // ---------- load x sample ----------
    {
        const float4* xg = (const float4*)(x + (size_t)s * (P_ * Q_));
        float4* sx4 = (float4*)sx;
        for (int i = tid; i < (P_ * Q_) / 4; i += THREADS) sx4[i] = xg[i];
    }
    for (int i = tid; i < Q_ * CB_; i += THREADS) sCk[i] = cf[i];
    __syncthreads();

    // ---------- carriage 1: y1[p,b] = sum_q x[p,q] cf[q,b] (into sM[p*8+b]) ----------
    for (int e = tid; e < P_ * CB_; e += THREADS) {
        int p = e >> 3, b = e & 7;
        const float* xp = sx + p * Q_;
        float acc = 0.f;
        #pragma unroll
        for (int q = 0; q < Q_; q++) acc += xp[q] * sCk[q * 8 + b];
        sM[e] = acc;
    }
    __syncthreads();

    // state0[b,r,c] = sum_p y1[p,b] * tf[c,p,r]   (threads 0..255)
    if (tid < 256) {
        const int b = tid >> 5, r = tid & 31;
        float acc[C_];
        #pragma unroll
        for (int c = 0; c < C_; c++) acc[c] = 0.f;
        for (int p = 0; p < P_; p++) {
            float y = sM[p * 8 + b];
            #pragma unroll
            for (int c = 0; c < C_; c++)
                acc[c] += y * tf[((size_t)c * P_ + p) * R_ + r];
        }
        #pragma unroll
        for (int c = 0; c < C_; c++) sState[b * 320 + r * 10 + c] = acc[c];
    }

    // ---------- mid carriages ----------
    // G-GEMM mapping: 16 row-groups x 64 col-groups; microtile 4 rows x 4 cols
    const int rowGrp = tid >> 6;        // 0..15 -> G rows ab = rowGrp*4..+3
    const int colGrp = tid & 63;        // 0..63 -> G cols colGrp*4..+3 (of 256)
    // update mapping: b(8) x r(32) x sub(4); sub = (ah<<1)|ch
    const int bU  = tid >> 7;
    const int rU  = (tid >> 2) & 31;
    const int chU = tid & 1;            // c half (5 each)
    const int ahU = (tid >> 1) & 1;     // a half (4 each)

    for (int k = 0; k < NMID; k++) {
        const float* Ck = cm + (size_t)k * (CB_ * Q_ * CB_);
        const float* Ak = tm + (size_t)k * (R_ * P_ * R_);
        float* stCur = sState + (k & 1) * 2560;
        float* stNxt = sState + ((k & 1) ^ 1) * 2560;

        __syncthreads();  // state writes + partial-combine reads of sG done

        // Ck -> sCk as [q][a*8+b]
        for (int i = tid; i < CB_ * Q_ * CB_; i += THREADS) {
            int a  = i / (Q_ * CB_);
            int qb = i % (Q_ * CB_);
            int q = qb >> 3, b = qb & 7;
            sCk[q * 64 + a * 8 + b] = Ck[i];
        }
        __syncthreads();

        // M[p][ab] = sum_q x[p,q] * Ck[a,q,b]
        for (int e4 = tid; e4 < (P_ * 64) / 4; e4 += THREADS) {
            int p  = e4 >> 4;
            int c4 = e4 & 15;
            const float*  xp  = sx + p * Q_;
            const float4* ck4 = ((const float4*)sCk) + c4;
            float4 acc = make_float4(0.f, 0.f, 0.f, 0.f);
            #pragma unroll
            for (int q = 0; q < Q_; q++) {
                float  f  = xp[q];
                float4 cv = ck4[q * 16];
                acc.x += f * cv.x; acc.y += f * cv.y;
                acc.z += f * cv.z; acc.w += f * cv.w;
            }
            ((float4*)sM)[e4] = acc;
        }

        float ns[5];
        #pragma unroll
        for (int c = 0; c < 5; c++) ns[c] = 0.f;

        // 4 tiles over groups of 8 l-values; G tile [64 rows][8*32 cols]
        for (int lt = 0; lt < 4; lt++) {
            __syncthreads();  // sM ready (lt=0) / prev tile's G reads done

            const int   l   = lt * 8 + (colGrp >> 3);
            const int   r0  = (colGrp & 7) * 4;
            const float* AkL = Ak + (size_t)l * (P_ * R_) + r0;
            // this thread's 4 M-rows = one ulonglong2 (2 packed pairs) per p
            const ulonglong2* mbase = ((const ulonglong2*)sM) + rowGrp;

            uint64_t acc[8];
            #pragma unroll
            for (int i = 0; i < 8; i++) acc[i] = 0ull;

            // unroll-2 p loop, av prefetch distance 2, m distance 1; no predication
            float4     av0 = *(const float4*)(AkL + 0 * R_);
            float4     av1 = *(const float4*)(AkL + 1 * R_);
            ulonglong2 ma  = mbase[0];

            #pragma unroll 1
            for (int pb = 0; pb < P_ - 2; pb += 2) {
                float4     avn0 = *(const float4*)(AkL + (pb + 2) * R_);
                ulonglong2 ma1  = mbase[(pb + 1) * MSTRIDE];
                FFMA2_BLK8(acc, ma, av0)
                float4     avn1 = *(const float4*)(AkL + (pb + 3) * R_);
                ulonglong2 ma2  = mbase[(pb + 2) * MSTRIDE];
                FFMA2_BLK8(acc, ma1, av1)
                av0 = avn0; av1 = avn1; ma = ma2;
            }
            // tail: p = 194, 195
            {
                ulonglong2 ma1 = mbase[195 * MSTRIDE];
                FFMA2_BLK8(acc, ma, av0)
                FFMA2_BLK8(acc, ma1, av1)
            }

            // write 4 rows x 4 cols to G
            float4* g4 = (float4*)sG;
            #pragma unroll
            for (int pr = 0; pr < 2; pr++) {
                float2 l0 = unpack2(acc[pr * 4 + 0]);
                float2 l1 = unpack2(acc[pr * 4 + 1]);
                float2 l2 = unpack2(acc[pr * 4 + 2]);
                float2 l3 = unpack2(acc[pr * 4 + 3]);
                g4[(rowGrp * 4 + pr * 2 + 0) * 64 + colGrp] =
                    make_float4(l0.x, l1.x, l2.x, l3.x);
                g4[(rowGrp * 4 + pr * 2 + 1) * 64 + colGrp] =
                    make_float4(l0.y, l1.y, l2.y, l3.y);
            }
            __syncthreads();  // G tile complete

            // partial: ns[c] += sum_{a in a-half, lj} state[a, lt*8+lj, c-half] * G[...]
            #pragma unroll
            for (int aa = 0; aa < 4; aa++) {
                const int a = ahU * 4 + aa;
                #pragma unroll
                for (int lj = 0; lj < 8; lj++) {
                    float g = sG[(a * 8 + bU) * 256 + lj * 32 + rU];
                    const float* st = stCur + a * 320 + (lt * 8 + lj) * 10 + chU * 5;
                    #pragma unroll
                    for (int c = 0; c < 5; c++) ns[c] += st[c] * g;
                }
            }
        }

        // combine a-half partials via sG (free now) and write stNxt
        __syncthreads();  // all tile reads of sG done
        #pragma unroll
        for (int c = 0; c < 5; c++) sG[tid * 5 + c] = ns[c];
        __syncthreads();
        if (ahU == 0) {
            #pragma unroll
            for (int c = 0; c < 5; c++)
                stNxt[bU * 320 + rU * 10 + chU * 5 + c] =
                    ns[c] + sG[(tid + 2) * 5 + c];
        }
    }

    // ---------- last carriage ----------
    __syncthreads();

    // z[p,a] = sum_q x[p,q] cl[a,q]  (into sM[p*8+a])
    for (int e = tid; e < P_ * CB_; e += THREADS) {
        int p = e >> 3, a = e & 7;
        const float* xp  = sx + p * Q_;
        const float* cla = cl + a * Q_;
        float acc = 0.f;
        #pragma unroll
        for (int q = 0; q < Q_; q++) acc += xp[q] * cla[q];
        sM[e] = acc;
    }
    if (tid < C_) sOut[tid] = 0.f;
    __syncthreads();

    // GN[a,l] = sum_p z[p,a] tl[l,p];  out[c] = sum_{a,l} state[a,l,c]*GN[a,l]
    if (tid < 256) {
        const int a = tid >> 5, l = tid & 31;
        const float* tlr = tl + l * P_;
        float gn = 0.f;
        for (int p = 0; p < P_; p++) gn += sM[p * 8 + a] * tlr[p];

        const float* st = sState + /*final buffer 0 (NMID even)*/ a * 320 + l * 10;
        #pragma unroll
        for (int c = 0; c < C_; c++) atomicAdd(&sOut[c], st[c] * gn);
    }
    __syncthreads();

    if (tid < C_) out[(size_t)s * C_ + tid] = sOut[tid];
}

extern "C" void kernel_launch(void* const* d_in, const int* in_sizes, int n_in,
                              void* d_out, int out_size)
{
    const float* x  = (const float*)d_in[0];
    const float* cf = (const float*)d_in[1];
    const float* cm = (const float*)d_in[2];
    const float* cl = (const float*)d_in[3];
    const float* tf = (const float*)d_in[4];
    const float* tm = (const float*)d_in[5];
    const float* tl = (const float*)d_in[6];
    float* out = (float*)d_out;

    size_t shbytes = SMEM_FLOATS * sizeof(float);
    cudaFuncSetAttribute(tctl_kernel, cudaFuncAttributeMaxDynamicSharedMemorySize,
                         (int)shbytes);
    tctl_kernel<<<S_, THREADS, shbytes>>>(x, cf, cm, cl, tf, tm, tl, out);
}